// round 1
// baseline (speedup 1.0000x reference)
#include <cuda_runtime.h>

typedef unsigned long long u64;

__device__ __forceinline__ u64 pack2(float lo, float hi) {
    u64 r;
    asm("mov.b64 %0, {%1, %2};" : "=l"(r) : "r"(__float_as_uint(lo)), "r"(__float_as_uint(hi)));
    return r;
}
__device__ __forceinline__ void unpack2(u64 v, float& lo, float& hi) {
    unsigned int a, b;
    asm("mov.b64 {%0, %1}, %2;" : "=r"(a), "=r"(b) : "l"(v));
    lo = __uint_as_float(a);
    hi = __uint_as_float(b);
}
// Packed fp32x2 FMA (Blackwell FFMA2): d = a*b + c on both 32-bit halves.
__device__ __forceinline__ u64 ffma2(u64 a, u64 b, u64 c) {
    u64 d;
    asm("fma.rn.f32x2 %0, %1, %2, %3;" : "=l"(d) : "l"(a), "l"(b), "l"(c));
    return d;
}
__device__ __forceinline__ float tanh_fast(float x) {
    float y;
    asm("tanh.approx.f32 %0, %1;" : "=f"(y) : "f"(x));
    return y;
}

// Systolic 4-layer tanh RNN.
// Thread g: layer = g & 3, batch = g >> 2. Lane L handles layer L&3, so within a
// warp 8 batch elements x 4 layers. Layer l at iteration i computes timestep
// t = i - l, consuming layer (l-1)'s hidden state (shuffled up one lane) which
// was produced at iteration i-1 (same t). All lanes run identical code; layer
// differences live entirely in per-lane register values (weights).
__global__ void __launch_bounds__(128, 1) rnn4_kernel(
    const float* __restrict__ x,        // [T, B]
    const float* __restrict__ h0,       // [4, B, 8]
    const float* __restrict__ W_ih0,    // [8, 1]
    const float* __restrict__ W_ih_rest,// [3, 8, 8]
    const float* __restrict__ W_hh,     // [4, 8, 8]
    const float* __restrict__ b_ih,     // [4, 8]
    const float* __restrict__ b_hh,     // [4, 8]
    const float* __restrict__ W_out,    // [1, 8]
    const float* __restrict__ b_out,    // [1]
    float* __restrict__ out,            // [B]
    int T, int B)
{
    const int g     = blockIdx.x * blockDim.x + threadIdx.x;
    const int layer = g & 3;
    const int b     = g >> 2;
    if (b >= B) return;
    const bool l0 = (layer == 0);

    // Weights packed along output-unit pairs: wi[k][jp] = (Wi[2jp][k], Wi[2jp+1][k]).
    // Layer 0's input is scalar x_t; treat as 8-vector (x,0,..,0) with Wi col 0 = W_ih0.
    u64 wi[8][4], wh[8][4], bias[4];
    #pragma unroll
    for (int jp = 0; jp < 4; ++jp) {
        const int j0 = 2 * jp, j1 = j0 + 1;
        #pragma unroll
        for (int k = 0; k < 8; ++k) {
            float a0, a1;
            if (l0) {
                a0 = (k == 0) ? W_ih0[j0] : 0.0f;
                a1 = (k == 0) ? W_ih0[j1] : 0.0f;
            } else {
                a0 = W_ih_rest[((layer - 1) * 8 + j0) * 8 + k];
                a1 = W_ih_rest[((layer - 1) * 8 + j1) * 8 + k];
            }
            wi[k][jp] = pack2(a0, a1);
            wh[k][jp] = pack2(W_hh[(layer * 8 + j0) * 8 + k],
                              W_hh[(layer * 8 + j1) * 8 + k]);
        }
        bias[jp] = pack2(b_ih[layer * 8 + j0] + b_hh[layer * 8 + j0],
                         b_ih[layer * 8 + j1] + b_hh[layer * 8 + j1]);
    }

    // Hidden state for this (batch, layer).
    float h[8];
    #pragma unroll
    for (int j = 0; j < 8; ++j) h[j] = h0[(layer * B + b) * 8 + j];

    const int NITER = T + 3;            // layer 3 finishes t=T-1 at i=T+2
    const int NI4   = (NITER + 3) & ~3; // round up for clean unroll-by-4

    // 4-deep x prefetch ring (layer-0 lanes only).
    float xr[4];
    #pragma unroll
    for (int p = 0; p < 4; ++p)
        xr[p] = (l0 && p < T) ? x[p * B + b] : 0.0f;
    const float* xp = x + (size_t)4 * B + b;

    for (int io = 0; io < NI4; io += 4) {
        #pragma unroll
        for (int u = 0; u < 4; ++u) {
            const int i = io + u;

            // Gather previous-layer output (produced last iteration) from lane-1.
            float in[8];
            #pragma unroll
            for (int j = 0; j < 8; ++j)
                in[j] = __shfl_up_sync(0xffffffffu, h[j], 1);

            u64 acc[4];
            #pragma unroll
            for (int jp = 0; jp < 4; ++jp) acc[jp] = bias[jp];

            // Input-weight matvec (layer 0 lanes substitute (x,0,..,0)).
            #pragma unroll
            for (int k = 0; k < 8; ++k) {
                const float s = l0 ? ((k == 0) ? xr[u] : 0.0f) : in[k];
                const u64 d = pack2(s, s);
                #pragma unroll
                for (int jp = 0; jp < 4; ++jp)
                    acc[jp] = ffma2(d, wi[k][jp], acc[jp]);
            }
            // Hidden-weight matvec (own pre-update state).
            #pragma unroll
            for (int k = 0; k < 8; ++k) {
                const u64 d = pack2(h[k], h[k]);
                #pragma unroll
                for (int jp = 0; jp < 4; ++jp)
                    acc[jp] = ffma2(d, wh[k][jp], acc[jp]);
            }

            const int  t     = i - layer;
            const bool valid = (t >= 0) && (t < T);
            #pragma unroll
            for (int jp = 0; jp < 4; ++jp) {
                float p0, p1;
                unpack2(acc[jp], p0, p1);
                const float n0 = tanh_fast(p0);
                const float n1 = tanh_fast(p1);
                if (valid) { h[2 * jp] = n0; h[2 * jp + 1] = n1; }
            }

            // Refill prefetch slot for iteration i+4.
            const bool pf = l0 && (i + 4 < T);
            xr[u] = pf ? __ldg(xp) : 0.0f;
            xp += B;
        }
    }

    // Readout: lanes holding layer 3 have h(t = T-1).
    if (layer == 3) {
        float acc = b_out[0];
        #pragma unroll
        for (int j = 0; j < 8; ++j)
            acc = fmaf(h[j], W_out[j], acc);
        out[b] = acc;
    }
}

extern "C" void kernel_launch(void* const* d_in, const int* in_sizes, int n_in,
                              void* d_out, int out_size) {
    const float* x         = (const float*)d_in[0];
    const float* h0        = (const float*)d_in[1];
    const float* W_ih0     = (const float*)d_in[2];
    const float* W_ih_rest = (const float*)d_in[3];
    const float* W_hh      = (const float*)d_in[4];
    const float* b_ih      = (const float*)d_in[5];
    const float* b_hh      = (const float*)d_in[6];
    const float* W_out     = (const float*)d_in[7];
    const float* b_out     = (const float*)d_in[8];

    const int B = in_sizes[1] / 32;   // h0: [4, B, 8]
    const int T = in_sizes[0] / B;    // x:  [T, B, 1]

    const int threads = 4 * B;
    const int block   = 128;
    const int grid    = (threads + block - 1) / block;

    rnn4_kernel<<<grid, block>>>(x, h0, W_ih0, W_ih_rest, W_hh, b_ih, b_hh,
                                 W_out, b_out, (float*)d_out, T, B);
}

// round 2
// speedup vs baseline: 1.1211x; 1.1211x over previous
#include <cuda_runtime.h>

typedef unsigned long long u64;

__device__ __forceinline__ u64 pack2(float lo, float hi) {
    u64 r;
    asm("mov.b64 %0, {%1, %2};" : "=l"(r) : "r"(__float_as_uint(lo)), "r"(__float_as_uint(hi)));
    return r;
}
__device__ __forceinline__ void unpack2(u64 v, float& lo, float& hi) {
    unsigned int a, b;
    asm("mov.b64 {%0, %1}, %2;" : "=r"(a), "=r"(b) : "l"(v));
    lo = __uint_as_float(a);
    hi = __uint_as_float(b);
}
// Packed fp32x2 FMA/ADD (Blackwell FFMA2).
__device__ __forceinline__ u64 ffma2(u64 a, u64 b, u64 c) {
    u64 d;
    asm("fma.rn.f32x2 %0, %1, %2, %3;" : "=l"(d) : "l"(a), "l"(b), "l"(c));
    return d;
}
__device__ __forceinline__ u64 add2(u64 a, u64 b) {
    u64 d;
    asm("add.rn.f32x2 %0, %1, %2;" : "=l"(d) : "l"(a), "l"(b));
    return d;
}
__device__ __forceinline__ float tanh_fast(float x) {
    float y;
    asm("tanh.approx.f32 %0, %1;" : "=f"(y) : "f"(x));
    return y;
}

// Systolic 4-layer tanh RNN. Lane L handles layer L&3; layer l at iteration i
// computes timestep t = i - l, consuming layer (l-1)'s previous-iteration
// output via __shfl_up(1). Split accumulators (input-matvec vs hidden-matvec)
// halve the FFMA dependency depth; guards exist only in the 4-iteration head
// (t<0 must keep h=h0) — the tail needs none because the loop ends exactly at
// layer 3's last timestep, and over-range layer 0-2 updates are unused and
// finite (tanh-bounded inputs, zero weights for layer-0's k>0 columns).
//
// ONE_STEP: HEADG = apply t>=0 guard on h update; PFG = guard x prefetch vs T.
#define ONE_STEP(IVAL, U, HEADG, PFG)                                          \
    do {                                                                       \
        const int i_ = (IVAL);                                                 \
        float in[8];                                                           \
        _Pragma("unroll")                                                      \
        for (int j = 0; j < 8; ++j)                                            \
            in[j] = __shfl_up_sync(0xffffffffu, h[j], 1);                      \
        u64 acc_i[4], acc_h[4];                                                \
        _Pragma("unroll")                                                      \
        for (int jp = 0; jp < 4; ++jp) { acc_h[jp] = bias[jp]; acc_i[jp] = zero64; } \
        /* hidden-matvec first: independent of the in-flight shfls */          \
        _Pragma("unroll")                                                      \
        for (int k = 0; k < 8; ++k) {                                          \
            const u64 d = pack2(h[k], h[k]);                                   \
            _Pragma("unroll")                                                  \
            for (int jp = 0; jp < 4; ++jp)                                     \
                acc_h[jp] = ffma2(d, wh[k][jp], acc_h[jp]);                    \
        }                                                                      \
        /* input-matvec: only k==0 needs the layer-0 select (wi==0 for k>0) */ \
        {                                                                      \
            const float s0 = l0 ? xr[U] : in[0];                               \
            const u64 d = pack2(s0, s0);                                       \
            _Pragma("unroll")                                                  \
            for (int jp = 0; jp < 4; ++jp)                                     \
                acc_i[jp] = ffma2(d, wi[0][jp], acc_i[jp]);                    \
        }                                                                      \
        _Pragma("unroll")                                                      \
        for (int k = 1; k < 8; ++k) {                                          \
            const u64 d = pack2(in[k], in[k]);                                 \
            _Pragma("unroll")                                                  \
            for (int jp = 0; jp < 4; ++jp)                                     \
                acc_i[jp] = ffma2(d, wi[k][jp], acc_i[jp]);                    \
        }                                                                      \
        _Pragma("unroll")                                                      \
        for (int jp = 0; jp < 4; ++jp) {                                       \
            float p0, p1;                                                      \
            unpack2(add2(acc_i[jp], acc_h[jp]), p0, p1);                       \
            const float n0 = tanh_fast(p0);                                    \
            const float n1 = tanh_fast(p1);                                    \
            if (HEADG) {                                                       \
                const bool valid = (i_ - layer) >= 0;                          \
                h[2 * jp]     = valid ? n0 : h[2 * jp];                        \
                h[2 * jp + 1] = valid ? n1 : h[2 * jp + 1];                    \
            } else {                                                           \
                h[2 * jp] = n0; h[2 * jp + 1] = n1;                            \
            }                                                                  \
        }                                                                      \
        if (PFG) xr[U] = (l0 && (i_ + 4) < T) ? __ldg(xp) : 0.0f;              \
        else     xr[U] = l0 ? __ldg(xp) : 0.0f;                                \
        xp += B;                                                               \
    } while (0)

__global__ void __launch_bounds__(128, 1) rnn4_kernel(
    const float* __restrict__ x,        // [T, B]
    const float* __restrict__ h0,       // [4, B, 8]
    const float* __restrict__ W_ih0,    // [8, 1]
    const float* __restrict__ W_ih_rest,// [3, 8, 8]
    const float* __restrict__ W_hh,     // [4, 8, 8]
    const float* __restrict__ b_ih,     // [4, 8]
    const float* __restrict__ b_hh,     // [4, 8]
    const float* __restrict__ W_out,    // [1, 8]
    const float* __restrict__ b_out,    // [1]
    float* __restrict__ out,            // [B]
    int T, int B)
{
    const int g     = blockIdx.x * blockDim.x + threadIdx.x;
    const int layer = g & 3;
    const int b     = g >> 2;
    if (b >= B) return;
    const bool l0 = (layer == 0);

    // Weights packed along output-unit pairs: wi[k][jp] = (Wi[2jp][k], Wi[2jp+1][k]).
    // Layer 0: Wi col 0 = W_ih0, cols 1..7 = 0 (input is scalar x_t).
    u64 wi[8][4], wh[8][4], bias[4];
    #pragma unroll
    for (int jp = 0; jp < 4; ++jp) {
        const int j0 = 2 * jp, j1 = j0 + 1;
        #pragma unroll
        for (int k = 0; k < 8; ++k) {
            float a0, a1;
            if (l0) {
                a0 = (k == 0) ? W_ih0[j0] : 0.0f;
                a1 = (k == 0) ? W_ih0[j1] : 0.0f;
            } else {
                a0 = W_ih_rest[((layer - 1) * 8 + j0) * 8 + k];
                a1 = W_ih_rest[((layer - 1) * 8 + j1) * 8 + k];
            }
            wi[k][jp] = pack2(a0, a1);
            wh[k][jp] = pack2(W_hh[(layer * 8 + j0) * 8 + k],
                              W_hh[(layer * 8 + j1) * 8 + k]);
        }
        bias[jp] = pack2(b_ih[layer * 8 + j0] + b_hh[layer * 8 + j0],
                         b_ih[layer * 8 + j1] + b_hh[layer * 8 + j1]);
    }
    const u64 zero64 = pack2(0.0f, 0.0f);

    // Hidden state for this (batch, layer).
    float h[8];
    #pragma unroll
    for (int j = 0; j < 8; ++j) h[j] = h0[(layer * B + b) * 8 + j];

    const int NITER = T + 3;            // layer 3 finishes t=T-1 at i=T+2

    // 4-deep x prefetch ring (layer-0 lanes only).
    float xr[4];
    #pragma unroll
    for (int p = 0; p < 4; ++p)
        xr[p] = (l0 && p < T) ? x[p * B + b] : 0.0f;
    const float* xp = x + (size_t)4 * B + b;

    // Phase 1: head, 4 guarded iterations (t<0 lanes hold h0).
    #pragma unroll
    for (int u = 0; u < 4; ++u)
        ONE_STEP(u, u, true, true);

    // Phase 2: main loop, no guards. Bound guarantees prefetch index i+4 < T.
    const int main_end = (T - 4) & ~3;  // multiple of 4; last group start <= T-8
    for (int io = 4; io < main_end; io += 4) {
        ONE_STEP(io + 0, 0, false, false);
        ONE_STEP(io + 1, 1, false, false);
        ONE_STEP(io + 2, 2, false, false);
        ONE_STEP(io + 3, 3, false, false);
    }

    // Phase 3: epilogue, guarded prefetch only (h guard provably unnecessary).
    for (int i = main_end; i < NITER; ++i)
        ONE_STEP(i, i & 3, false, true);

    // Readout: lanes holding layer 3 have h(t = T-1).
    if (layer == 3) {
        float acc = b_out[0];
        #pragma unroll
        for (int j = 0; j < 8; ++j)
            acc = fmaf(h[j], W_out[j], acc);
        out[b] = acc;
    }
}

extern "C" void kernel_launch(void* const* d_in, const int* in_sizes, int n_in,
                              void* d_out, int out_size) {
    const float* x         = (const float*)d_in[0];
    const float* h0        = (const float*)d_in[1];
    const float* W_ih0     = (const float*)d_in[2];
    const float* W_ih_rest = (const float*)d_in[3];
    const float* W_hh      = (const float*)d_in[4];
    const float* b_ih      = (const float*)d_in[5];
    const float* b_hh      = (const float*)d_in[6];
    const float* W_out     = (const float*)d_in[7];
    const float* b_out     = (const float*)d_in[8];

    const int B = in_sizes[1] / 32;   // h0: [4, B, 8]
    const int T = in_sizes[0] / B;    // x:  [T, B, 1]

    const int threads = 4 * B;
    const int block   = 128;
    const int grid    = (threads + block - 1) / block;

    rnn4_kernel<<<grid, block>>>(x, h0, W_ih0, W_ih_rest, W_hh, b_ih, b_hh,
                                 W_out, b_out, (float*)d_out, T, B);
}